// round 1
// baseline (speedup 1.0000x reference)
#include <cuda_runtime.h>
#include <cuda_bf16.h>
#include <cstddef>

// Problem constants
#define BQ 8192      // batch
#define NQ 784       // sites
#define MIDQ 392     // forward covers core steps 1..391 (cores_mid idx 0..390),
                     // backward covers core steps 392..782 (cores_mid idx 391..781)

// Scratch (static __device__ — no runtime allocation allowed)
__device__ float g_cosT[(size_t)NQ * BQ];   // [site][batch]
__device__ float g_sinT[(size_t)NQ * BQ];
__device__ float g_V[(size_t)BQ * 10];      // forward half-chain result v_mid
__device__ float g_U[(size_t)BQ * 10];      // backward half-chain result u_mid

// ---------------------------------------------------------------------------
// K1: featurize + transpose.  x:(B,N) row-major -> cosT/sinT:(N,B)
// Tiled 32x32 transpose so both global read (along n) and write (along b)
// are coalesced. sincospif gives exact sin(pi x), cos(pi x).
// ---------------------------------------------------------------------------
__global__ void feat_kernel(const float* __restrict__ x) {
    __shared__ float tc[32][33];
    __shared__ float ts[32][33];
    const int tx = threadIdx.x;
    const int ty = threadIdx.y;
    const int n0 = blockIdx.x * 32;
    const int b0 = blockIdx.y * 32;

    #pragma unroll
    for (int j = 0; j < 32; j += 8) {
        int n = n0 + tx;            // coalesced along n
        int b = b0 + ty + j;
        if (n < NQ) {
            float val = x[(size_t)b * NQ + n];
            float s, c;
            sincospif(val, &s, &c);
            tc[tx][ty + j] = c;     // sm[n_local][b_local]
            ts[tx][ty + j] = s;
        }
    }
    __syncthreads();
    #pragma unroll
    for (int j = 0; j < 32; j += 8) {
        int n = n0 + ty + j;
        int b = b0 + tx;            // coalesced along b
        if (n < NQ) {
            g_cosT[(size_t)n * BQ + b] = tc[ty + j][tx];
            g_sinT[(size_t)n * BQ + b] = ts[ty + j][tx];
        }
    }
}

// ---------------------------------------------------------------------------
// K2: the chain. 16384 threads: t < 8192 propagate forward from site 0 to the
// middle; t >= 8192 propagate backward from site 783 to the middle.
// cores_mid[i][l][d][r]: row (l) = 20 contiguous floats: [0..9]=d0 (cos),
// [10..19]=d1 (sin). Loaded as 5 x float4 per row, same address across the
// warp -> L1 broadcast.
// ---------------------------------------------------------------------------
__global__ __launch_bounds__(128, 1)
void chain_kernel(const float* __restrict__ core_first,
                  const float* __restrict__ cores_mid,
                  const float* __restrict__ core_last) {
    const int t = blockIdx.x * blockDim.x + threadIdx.x;
    const bool fwd = (t < BQ);
    const int b = fwd ? t : (t - BQ);

    float v[10];

    if (fwd) {
        // v = feats[:,0] @ core_first[0]   (core_first flat: [d*10 + l])
        const float c0 = g_cosT[b];
        const float s0 = g_sinT[b];
        #pragma unroll
        for (int l = 0; l < 10; l++)
            v[l] = c0 * __ldg(core_first + l) + s0 * __ldg(core_first + 10 + l);

        for (int i = 1; i < MIDQ; i++) {
            const float fc = g_cosT[(size_t)i * BQ + b];
            const float fs = g_sinT[(size_t)i * BQ + b];
            const float4* row = (const float4*)(cores_mid + (size_t)(i - 1) * 200);

            float t0[10], t1[10];
            #pragma unroll
            for (int r = 0; r < 10; r++) { t0[r] = 0.f; t1[r] = 0.f; }

            #pragma unroll
            for (int l = 0; l < 10; l++) {
                const float4 q0 = __ldg(row + l * 5 + 0);
                const float4 q1 = __ldg(row + l * 5 + 1);
                const float4 q2 = __ldg(row + l * 5 + 2);
                const float4 q3 = __ldg(row + l * 5 + 3);
                const float4 q4 = __ldg(row + l * 5 + 4);
                const float vl = v[l];
                t0[0] += vl * q0.x; t0[1] += vl * q0.y; t0[2] += vl * q0.z; t0[3] += vl * q0.w;
                t0[4] += vl * q1.x; t0[5] += vl * q1.y; t0[6] += vl * q1.z; t0[7] += vl * q1.w;
                t0[8] += vl * q2.x; t0[9] += vl * q2.y;
                t1[0] += vl * q2.z; t1[1] += vl * q2.w;
                t1[2] += vl * q3.x; t1[3] += vl * q3.y; t1[4] += vl * q3.z; t1[5] += vl * q3.w;
                t1[6] += vl * q4.x; t1[7] += vl * q4.y; t1[8] += vl * q4.z; t1[9] += vl * q4.w;
            }
            #pragma unroll
            for (int r = 0; r < 10; r++) v[r] = fc * t0[r] + fs * t1[r];
        }
        #pragma unroll
        for (int l = 0; l < 10; l++) g_V[(size_t)b * 10 + l] = v[l];
    } else {
        // u_783[l] = sum_d feats[:,783,d] * core_last[l,d]  (core_last flat [l*2+d])
        const float cl = g_cosT[(size_t)(NQ - 1) * BQ + b];
        const float sl = g_sinT[(size_t)(NQ - 1) * BQ + b];
        #pragma unroll
        for (int l = 0; l < 10; l++)
            v[l] = cl * __ldg(core_last + l * 2) + sl * __ldg(core_last + l * 2 + 1);

        // u_i = M_i u_{i+1}:  u_new[l] = fc*dot(A[l,:],u) + fs*dot(B[l,:],u)
        for (int i = NQ - 2; i >= MIDQ; i--) {      // i = 782 .. 392
            const float fc = g_cosT[(size_t)i * BQ + b];
            const float fs = g_sinT[(size_t)i * BQ + b];
            const float4* row = (const float4*)(cores_mid + (size_t)(i - 1) * 200);

            float un[10];
            #pragma unroll
            for (int l = 0; l < 10; l++) {
                const float4 q0 = __ldg(row + l * 5 + 0);
                const float4 q1 = __ldg(row + l * 5 + 1);
                const float4 q2 = __ldg(row + l * 5 + 2);
                const float4 q3 = __ldg(row + l * 5 + 3);
                const float4 q4 = __ldg(row + l * 5 + 4);
                float a  = q0.x * v[0] + q0.y * v[1] + q0.z * v[2] + q0.w * v[3]
                         + q1.x * v[4] + q1.y * v[5] + q1.z * v[6] + q1.w * v[7]
                         + q2.x * v[8] + q2.y * v[9];
                float bb = q2.z * v[0] + q2.w * v[1]
                         + q3.x * v[2] + q3.y * v[3] + q3.z * v[4] + q3.w * v[5]
                         + q4.x * v[6] + q4.y * v[7] + q4.z * v[8] + q4.w * v[9];
                un[l] = fc * a + fs * bb;
            }
            #pragma unroll
            for (int l = 0; l < 10; l++) v[l] = un[l];
        }
        #pragma unroll
        for (int l = 0; l < 10; l++) g_U[(size_t)b * 10 + l] = v[l];
    }
}

// ---------------------------------------------------------------------------
// K3: s[b] = dot(v_mid, u_mid);  logits[b,c] = s[b] * sum_d OT[c,d,0]
// (the reference einsum broadcasts result's size-1 'd' against BD=10)
// ---------------------------------------------------------------------------
__global__ void combine_kernel(const float* __restrict__ ot,
                               float* __restrict__ out) {
    const int b = blockIdx.x * blockDim.x + threadIdx.x;
    if (b >= BQ) return;
    float s = 0.f;
    #pragma unroll
    for (int l = 0; l < 10; l++)
        s += g_V[(size_t)b * 10 + l] * g_U[(size_t)b * 10 + l];
    #pragma unroll
    for (int c = 0; c < 10; c++) {
        float w = 0.f;
        #pragma unroll
        for (int d = 0; d < 10; d++) w += __ldg(ot + c * 10 + d);
        out[(size_t)b * 10 + c] = s * w;
    }
}

// ---------------------------------------------------------------------------
extern "C" void kernel_launch(void* const* d_in, const int* in_sizes, int n_in,
                              void* d_out, int out_size) {
    const float* x          = (const float*)d_in[0];  // (8192, 784)
    const float* core_first = (const float*)d_in[1];  // (1, 2, 10)
    const float* cores_mid  = (const float*)d_in[2];  // (782, 10, 2, 10)
    const float* core_last  = (const float*)d_in[3];  // (10, 2, 1)
    const float* out_t      = (const float*)d_in[4];  // (10, 10, 1)
    float* out = (float*)d_out;                       // (8192, 10)

    dim3 fgrid((NQ + 31) / 32, BQ / 32);
    dim3 fblk(32, 8);
    feat_kernel<<<fgrid, fblk>>>(x);

    chain_kernel<<<(2 * BQ) / 128, 128>>>(core_first, cores_mid, core_last);

    combine_kernel<<<BQ / 256, 256>>>(out_t, out);
}

// round 3
// speedup vs baseline: 1.0786x; 1.0786x over previous
#include <cuda_runtime.h>
#include <cuda_bf16.h>
#include <cstddef>

#define BQ 8192      // batch
#define NQ 784       // sites
#define MIDQ 392     // forward: steps 1..391 ; backward: steps 782..392

typedef unsigned long long ull;

// Scratch (static; 16B-aligned where vector-loaded)
__device__ float2     g_feat[(size_t)NQ * BQ];        // [site][batch] (cos, sin)
__device__ ulonglong2 g_coresT[(size_t)(NQ - 2) * 50];// transposed cores (backward), 50 u2/site
__device__ ull        g_V[(size_t)BQ * 5];            // forward half result (pairs)
__device__ ull        g_U[(size_t)BQ * 5];            // backward half result (pairs)

// ---------------- packed f32x2 helpers ----------------
__device__ __forceinline__ ull pack2(float lo, float hi) {
    ull r;
    asm("mov.b64 %0, {%1, %2};" : "=l"(r)
        : "r"(__float_as_uint(lo)), "r"(__float_as_uint(hi)));
    return r;
}
__device__ __forceinline__ float2 unpack2(ull v) {
    unsigned int lo, hi;
    asm("mov.b64 {%0, %1}, %2;" : "=r"(lo), "=r"(hi) : "l"(v));
    return make_float2(__uint_as_float(lo), __uint_as_float(hi));
}
__device__ __forceinline__ ull fma2(ull a, ull b, ull c) {
    ull d;
    asm("fma.rn.f32x2 %0, %1, %2, %3;" : "=l"(d) : "l"(a), "l"(b), "l"(c));
    return d;
}
__device__ __forceinline__ ull mul2(ull a, ull b) {
    ull d;
    asm("mul.rn.f32x2 %0, %1, %2;" : "=l"(d) : "l"(a), "l"(b));
    return d;
}

// ---------------------------------------------------------------------------
// K1: featurize + transpose. x:(B,N) -> g_feat:(N,B) float2 (cos, sin)
// ---------------------------------------------------------------------------
__global__ void feat_kernel(const float* __restrict__ x) {
    __shared__ float2 tf[32][33];
    const int tx = threadIdx.x;
    const int ty = threadIdx.y;
    const int n0 = blockIdx.x * 32;
    const int b0 = blockIdx.y * 32;

    #pragma unroll
    for (int j = 0; j < 32; j += 8) {
        int n = n0 + tx;
        int b = b0 + ty + j;
        if (n < NQ) {
            float val = x[(size_t)b * NQ + n];
            float s, c;
            sincospif(val, &s, &c);
            tf[tx][ty + j] = make_float2(c, s);
        }
    }
    __syncthreads();
    #pragma unroll
    for (int j = 0; j < 32; j += 8) {
        int n = n0 + ty + j;
        int b = b0 + tx;
        if (n < NQ) g_feat[(size_t)n * BQ + b] = tf[ty + j][tx];
    }
}

// ---------------------------------------------------------------------------
// K1b: transpose cores for the backward half.
// src[i][l][d][r] (200 floats/site) -> dst[i][r][d][l]
// ---------------------------------------------------------------------------
__global__ void transpose_cores(const float* __restrict__ src) {
    const int site = blockIdx.x;
    const int o = threadIdx.x;          // 0..199 : o = r*20 + d*10 + l
    const int r = o / 20;
    const int d = (o % 20) / 10;
    const int l = o % 10;
    ((float*)g_coresT)[(size_t)site * 200 + o] =
        src[(size_t)site * 200 + l * 20 + d * 10 + r];
}

// ---------------------------------------------------------------------------
// Generic half-chain, packed f32x2. vp[j] holds pair (v[2j], v[2j+1]).
// Per-step row layout for input index 'l': 20 floats = [M0 out0..9][M1 out0..9]
// = 5 ulonglong2. One site = 10 rows = 50 ulonglong2 (800 B).
// ---------------------------------------------------------------------------
__device__ __forceinline__ void half_chain(const ulonglong2* __restrict__ row,
                                           const float2* __restrict__ fp,
                                           int nsteps, int dir,
                                           ull vp[5]) {
    const long rstep = (long)dir * 50;     // 50 ulonglong2 per site  (bug fixed)
    const long fstep = (long)dir * BQ;

    for (int k = 0; k < nsteps; k++) {
        const float2 f = *fp;
        float2 vf0 = unpack2(vp[0]);
        float2 vf1 = unpack2(vp[1]);
        float2 vf2 = unpack2(vp[2]);
        float2 vf3 = unpack2(vp[3]);
        float2 vf4 = unpack2(vp[4]);

        ull a0, a1, a2, a3, a4, c0, c1, c2, c3, c4;

        #pragma unroll
        for (int l = 0; l < 10; l++) {
            const ulonglong2 p0 = __ldg(row + l * 5 + 0);
            const ulonglong2 p1 = __ldg(row + l * 5 + 1);
            const ulonglong2 p2 = __ldg(row + l * 5 + 2);
            const ulonglong2 p3 = __ldg(row + l * 5 + 3);
            const ulonglong2 p4 = __ldg(row + l * 5 + 4);
            float vl;
            switch (l) {
                case 0: vl = vf0.x; break; case 1: vl = vf0.y; break;
                case 2: vl = vf1.x; break; case 3: vl = vf1.y; break;
                case 4: vl = vf2.x; break; case 5: vl = vf2.y; break;
                case 6: vl = vf3.x; break; case 7: vl = vf3.y; break;
                case 8: vl = vf4.x; break; default: vl = vf4.y; break;
            }
            const ull vl2 = pack2(vl, vl);
            if (l == 0) {
                a0 = mul2(vl2, p0.x); a1 = mul2(vl2, p0.y);
                a2 = mul2(vl2, p1.x); a3 = mul2(vl2, p1.y);
                a4 = mul2(vl2, p2.x);
                c0 = mul2(vl2, p2.y);
                c1 = mul2(vl2, p3.x); c2 = mul2(vl2, p3.y);
                c3 = mul2(vl2, p4.x); c4 = mul2(vl2, p4.y);
            } else {
                a0 = fma2(vl2, p0.x, a0); a1 = fma2(vl2, p0.y, a1);
                a2 = fma2(vl2, p1.x, a2); a3 = fma2(vl2, p1.y, a3);
                a4 = fma2(vl2, p2.x, a4);
                c0 = fma2(vl2, p2.y, c0);
                c1 = fma2(vl2, p3.x, c1); c2 = fma2(vl2, p3.y, c2);
                c3 = fma2(vl2, p4.x, c3); c4 = fma2(vl2, p4.y, c4);
            }
        }
        const ull fc2 = pack2(f.x, f.x);
        const ull fs2 = pack2(f.y, f.y);
        vp[0] = fma2(fs2, c0, mul2(fc2, a0));
        vp[1] = fma2(fs2, c1, mul2(fc2, a1));
        vp[2] = fma2(fs2, c2, mul2(fc2, a2));
        vp[3] = fma2(fs2, c3, mul2(fc2, a3));
        vp[4] = fma2(fs2, c4, mul2(fc2, a4));

        row += rstep;
        fp += fstep;
    }
}

// ---------------------------------------------------------------------------
// K2: the chain. t<BQ: forward from site 0 to middle; else backward.
// block=128 so the 4 warps cover all 4 SMSPs (wid%4).
// ---------------------------------------------------------------------------
__global__ __launch_bounds__(128, 1)
void chain_kernel(const float* __restrict__ core_first,
                  const float* __restrict__ cores_mid,
                  const float* __restrict__ core_last) {
    const int t = blockIdx.x * blockDim.x + threadIdx.x;
    const bool fwd = (t < BQ);
    const int b = fwd ? t : (t - BQ);

    ull vp[5];

    if (fwd) {
        // v = feats[:,0] @ core_first[0] ; core_first flat [d*10 + l]
        const float2 f0 = g_feat[b];
        const ull* cfc = (const ull*)core_first;        // cos part, 5 pairs
        const ull* cfs = (const ull*)(core_first + 10); // sin part, 5 pairs
        const ull c02 = pack2(f0.x, f0.x);
        const ull s02 = pack2(f0.y, f0.y);
        #pragma unroll
        for (int j = 0; j < 5; j++)
            vp[j] = fma2(s02, __ldg(cfs + j), mul2(c02, __ldg(cfc + j)));

        half_chain((const ulonglong2*)cores_mid, g_feat + (size_t)BQ + b,
                   MIDQ - 1, +1, vp);

        #pragma unroll
        for (int j = 0; j < 5; j++) g_V[(size_t)b * 5 + j] = vp[j];
    } else {
        // u_783[l] = fc*core_last[l][0] + fs*core_last[l][1]
        const float2 fL = g_feat[(size_t)(NQ - 1) * BQ + b];
        const float2* cl = (const float2*)core_last;
        #pragma unroll
        for (int j = 0; j < 5; j++) {
            float2 qa = __ldg(cl + 2 * j);
            float2 qb = __ldg(cl + 2 * j + 1);
            vp[j] = pack2(fL.x * qa.x + fL.y * qa.y,
                          fL.x * qb.x + fL.y * qb.y);
        }

        // backward: sites 782..392, transposed mats (site idx 781..391)
        half_chain(g_coresT + (size_t)(NQ - 3) * 50,
                   g_feat + (size_t)(NQ - 2) * BQ + b, NQ - 1 - MIDQ, -1, vp);

        #pragma unroll
        for (int j = 0; j < 5; j++) g_U[(size_t)b * 5 + j] = vp[j];
    }
}

// ---------------------------------------------------------------------------
// K3: s[b] = dot(v,u);  logits[b,c] = s[b] * sum_d OT[c,d,0]
// ---------------------------------------------------------------------------
__global__ void combine_kernel(const float* __restrict__ ot,
                               float* __restrict__ out) {
    const int b = blockIdx.x * blockDim.x + threadIdx.x;
    if (b >= BQ) return;
    float s = 0.f;
    #pragma unroll
    for (int j = 0; j < 5; j++) {
        float2 a = unpack2(g_V[(size_t)b * 5 + j]);
        float2 u = unpack2(g_U[(size_t)b * 5 + j]);
        s += a.x * u.x + a.y * u.y;
    }
    #pragma unroll
    for (int c = 0; c < 10; c++) {
        float w = 0.f;
        #pragma unroll
        for (int d = 0; d < 10; d++) w += __ldg(ot + c * 10 + d);
        out[(size_t)b * 10 + c] = s * w;
    }
}

// ---------------------------------------------------------------------------
extern "C" void kernel_launch(void* const* d_in, const int* in_sizes, int n_in,
                              void* d_out, int out_size) {
    const float* x          = (const float*)d_in[0];  // (8192, 784)
    const float* core_first = (const float*)d_in[1];  // (1, 2, 10)
    const float* cores_mid  = (const float*)d_in[2];  // (782, 10, 2, 10)
    const float* core_last  = (const float*)d_in[3];  // (10, 2, 1)
    const float* out_t      = (const float*)d_in[4];  // (10, 10, 1)
    float* out = (float*)d_out;                       // (8192, 10)

    dim3 fgrid((NQ + 31) / 32, BQ / 32);
    dim3 fblk(32, 8);
    feat_kernel<<<fgrid, fblk>>>(x);
    transpose_cores<<<NQ - 2, 200>>>(cores_mid);

    chain_kernel<<<(2 * BQ) / 128, 128>>>(core_first, cores_mid, core_last);

    combine_kernel<<<BQ / 256, 256>>>(out_t, out);
}